// round 9
// baseline (speedup 1.0000x reference)
#include <cuda_runtime.h>
#include <cstdint>

// Problem constants: B=32, N=M=4096, d=3
#define BB     32
#define NPTS   4096
#define NCLUS  128
#define CSZ    32                 // targets per cluster
#define NBINS  4096               // 12-bit morton (16^3 grid)
#define P3_TPB 256
#define NBLK1  128                // stage-1 reduce blocks

#define BIGF 3.4028235e38f

// ---- persistent scratch (no allocations allowed) --------------------------
__device__ float4 g_tgtS [BB * NPTS];   // binned targets {x, y, z, 0.5|t|^2}
__device__ float4 g_predS[BB * NPTS];   // binned preds  {-x,-y,-z,  |p|^2}
__device__ int    g_pidx [BB * NPTS];   // original pred index per binned slot
__device__ float4 g_clusC[BB * NCLUS];  // cluster {cx, cy, cz, 0.5|c|^2}
__device__ float  g_clusR[BB * NCLUS];  // cluster radius (inflated)
__device__ float  g_dist [BB * NPTS];   // per-pred nearest distance (orig order)
__device__ float  g_bsum [NBLK1];       // stage-1 partial sums

// ---------------------------------------------------------------------------
__device__ __forceinline__ unsigned morton12(float x, float y, float z) {
    int qx = min(max(__float2int_rd((x + 4.0f) * 2.0f), 0), 15);
    int qy = min(max(__float2int_rd((y + 4.0f) * 2.0f), 0), 15);
    int qz = min(max(__float2int_rd((z + 4.0f) * 2.0f), 0), 15);
    unsigned m = 0;
    #pragma unroll
    for (int b = 0; b < 4; b++) {
        m |= ((unsigned)((qx >> b) & 1)) << (3 * b + 2);
        m |= ((unsigned)((qy >> b) & 1)) << (3 * b + 1);
        m |= ((unsigned)((qz >> b) & 1)) << (3 * b + 0);
    }
    return m;
}

// ---------------------------------------------------------------------------
// P1: morton counting-sort (binning). One CTA per (batch, tensor).
// blockIdx.x: bit0 = isPred, rest = batch.
// ---------------------------------------------------------------------------
__global__ __launch_bounds__(512) void bin_kernel(const float* __restrict__ pred,
                                                  const float* __restrict__ tgt) {
    __shared__ unsigned hist[NBINS];   // 16 KB
    __shared__ unsigned wsum[512];

    int b      = blockIdx.x >> 1;
    int isPred = blockIdx.x & 1;
    const float* src = (isPred ? pred : tgt) + (size_t)b * NPTS * 3;
    int tid = threadIdx.x;

    #pragma unroll
    for (int j = 0; j < NBINS / 512; j++) hist[tid + j * 512] = 0u;
    __syncthreads();

    // Phase A: histogram (8 points per thread)
    unsigned mybin[8];
    #pragma unroll
    for (int j = 0; j < 8; j++) {
        int i = tid * 8 + j;
        float x = src[3 * i], y = src[3 * i + 1], z = src[3 * i + 2];
        mybin[j] = morton12(x, y, z);
        atomicAdd(&hist[mybin[j]], 1u);
    }
    __syncthreads();

    // Phase B: exclusive scan over 4096 bins (8 serial + 512-wide block scan)
    unsigned s = 0;
    #pragma unroll
    for (int j = 0; j < 8; j++) s += hist[tid * 8 + j];
    wsum[tid] = s;
    __syncthreads();
    #pragma unroll
    for (int off = 1; off < 512; off <<= 1) {
        unsigned v = wsum[tid];
        unsigned a = (tid >= off) ? wsum[tid - off] : 0u;
        __syncthreads();
        wsum[tid] = v + a;
        __syncthreads();
    }
    unsigned run = wsum[tid] - s;          // exclusive base for this thread's bins
    #pragma unroll
    for (int j = 0; j < 8; j++) {
        unsigned c = hist[tid * 8 + j];
        hist[tid * 8 + j] = run;
        run += c;
    }
    __syncthreads();

    // Phase C: scatter (atomic rank within bin; output order within a bin is
    // arbitrary but the final result is order-invariant — see g_pidx path)
    float4* dst = (isPred ? g_predS : g_tgtS) + b * NPTS;
    int*    pix = g_pidx + b * NPTS;
    #pragma unroll
    for (int j = 0; j < 8; j++) {
        int i = tid * 8 + j;
        unsigned pos = atomicAdd(&hist[mybin[j]], 1u);
        float x = src[3 * i], y = src[3 * i + 1], z = src[3 * i + 2];
        float n2 = x * x + y * y + z * z;
        if (isPred) {
            dst[pos] = make_float4(-x, -y, -z, n2);
            pix[pos] = i;
        } else {
            dst[pos] = make_float4(x, y, z, 0.5f * n2);
        }
    }
}

// ---------------------------------------------------------------------------
// P2: per-cluster centroid + bounding radius (one warp per cluster)
// ---------------------------------------------------------------------------
__global__ __launch_bounds__(128) void cluster_kernel() {
    int gw   = (blockIdx.x * 128 + threadIdx.x) >> 5;
    int lane = threadIdx.x & 31;
    int b = gw >> 7, k = gw & (NCLUS - 1);

    float4 t = g_tgtS[b * NPTS + k * CSZ + lane];
    float cx = t.x, cy = t.y, cz = t.z;
    #pragma unroll
    for (int o = 16; o; o >>= 1) {
        cx += __shfl_xor_sync(0xffffffffu, cx, o);
        cy += __shfl_xor_sync(0xffffffffu, cy, o);
        cz += __shfl_xor_sync(0xffffffffu, cz, o);
    }
    cx *= (1.0f / 32.0f); cy *= (1.0f / 32.0f); cz *= (1.0f / 32.0f);

    float dx = t.x - cx, dy = t.y - cy, dz = t.z - cz;
    float d2 = dx * dx + dy * dy + dz * dz;
    #pragma unroll
    for (int o = 16; o; o >>= 1)
        d2 = fmaxf(d2, __shfl_xor_sync(0xffffffffu, d2, o));

    if (lane == 0) {
        g_clusC[b * NCLUS + k] = make_float4(cx, cy, cz, 0.5f * (cx * cx + cy * cy + cz * cz));
        g_clusR[b * NCLUS + k] = sqrtf(d2) * 1.0005f + 1e-6f;
    }
}

// ---------------------------------------------------------------------------
// P3: branch-and-bound nearest-target, warp-cooperative compact survivors.
//   r(p,t) = 0.5|t|^2 - p.t  (3 FFMA);  d^2 = |p|^2 + 2 r
// ---------------------------------------------------------------------------
__device__ __forceinline__ void eval_cluster(const float4* __restrict__ ct,
                                             float4 p, float& mR) {
    #pragma unroll 8
    for (int i = 0; i < CSZ; i++) {
        float4 t = ct[i];
        float r = __fmaf_rn(p.z, t.z, t.w);
        r = __fmaf_rn(p.y, t.y, r);
        r = __fmaf_rn(p.x, t.x, r);
        mR = fminf(mR, r);
    }
}

__global__ __launch_bounds__(P3_TPB) void chamfer_bb_kernel() {
    extern __shared__ float4 sT[];          // NPTS targets: 64 KB dynamic
    __shared__ float4 sC[NCLUS];
    __shared__ float  sR[NCLUS];

    int b     = blockIdx.x >> 4;            // 16 CTAs per batch
    int chunk = blockIdx.x & 15;
    int tid   = threadIdx.x;
    int lane  = tid & 31;

    const float4* gt = g_tgtS + b * NPTS;
    for (int i = tid; i < NPTS; i += P3_TPB) sT[i] = gt[i];
    if (tid < NCLUS) { sC[tid] = g_clusC[b * NCLUS + tid]; sR[tid] = g_clusR[b * NCLUS + tid]; }
    __syncthreads();

    int ip = chunk * P3_TPB + tid;          // pred rank (binned order)
    float4 p = g_predS[b * NPTS + ip];      // {-x,-y,-z, p2}
    int pidx = g_pidx [b * NPTS + ip];
    int k0   = ip >> 5;                     // positional probe cluster (warp-uniform)

    // probe: full evaluation of k0 -> per-lane upper bound u
    float mR = BIGF;
    eval_cluster(sT + k0 * CSZ, p, mR);
    float u = sqrtf(fmaxf(__fmaf_rn(2.0f, mR, p.w), 0.0f));

    // warp bound: max-u and bounding ball of the 32 preds (negated coords)
    float umax = u;
    float mnx = p.x, mxx = p.x, mny = p.y, mxy = p.y, mnz = p.z, mxz = p.z;
    #pragma unroll
    for (int o = 16; o; o >>= 1) {
        umax = fmaxf(umax, __shfl_xor_sync(0xffffffffu, umax, o));
        mnx = fminf(mnx, __shfl_xor_sync(0xffffffffu, mnx, o));
        mxx = fmaxf(mxx, __shfl_xor_sync(0xffffffffu, mxx, o));
        mny = fminf(mny, __shfl_xor_sync(0xffffffffu, mny, o));
        mxy = fmaxf(mxy, __shfl_xor_sync(0xffffffffu, mxy, o));
        mnz = fminf(mnz, __shfl_xor_sync(0xffffffffu, mnz, o));
        mxz = fmaxf(mxz, __shfl_xor_sync(0xffffffffu, mxz, o));
    }
    // actual-coordinate warp center q = -(mn+mx)/2 ; radius rho = |mx-mn|/2
    float qx = -0.5f * (mnx + mxx);
    float qy = -0.5f * (mny + mxy);
    float qz = -0.5f * (mnz + mxz);
    float hx = 0.5f * (mxx - mnx), hy = 0.5f * (mxy - mny), hz = 0.5f * (mxz - mnz);
    float rho = sqrtf(hx * hx + hy * hy + hz * hz);

    // survivor masks: lane tests clusters lane, lane+32, lane+64, lane+96
    unsigned masks[4];
    #pragma unroll
    for (int g = 0; g < 4; g++) {
        int k = g * 32 + lane;
        float4 c = sC[k];
        float dx = qx - c.x, dy = qy - c.y, dz = qz - c.z;
        float d2qc = dx * dx + dy * dy + dz * dz;
        float s = umax + sR[k] + rho;
        bool keep = d2qc <= __fmaf_rn(s * s, 1.0001f, 1e-6f);
        masks[g] = __ballot_sync(0xffffffffu, keep);
    }
    masks[k0 >> 5] &= ~(1u << (k0 & 31));   // probe already evaluated

    // evaluate survivors (warp-uniform mask walk — zero divergence)
    #pragma unroll
    for (int g = 0; g < 4; g++) {
        unsigned ms = masks[g];
        while (ms) {
            int k = g * 32 + (__ffs(ms) - 1);
            ms &= ms - 1;
            eval_cluster(sT + k * CSZ, p, mR);
        }
    }

    g_dist[b * NPTS + pidx] = sqrtf(fmaxf(__fmaf_rn(2.0f, mR, p.w), 0.0f));
}

// ---------------------------------------------------------------------------
// Reductions: fixed-order, deterministic
// ---------------------------------------------------------------------------
__global__ __launch_bounds__(256) void reduce1_kernel() {
    __shared__ float ssum[256];
    int tid = threadIdx.x;
    const int per_block = (BB * NPTS) / NBLK1;   // 1024
    float acc = 0.0f;
    #pragma unroll
    for (int k = 0; k < per_block / 256; k++)
        acc += g_dist[blockIdx.x * per_block + k * 256 + tid];
    ssum[tid] = acc;
    __syncthreads();
    #pragma unroll
    for (int s = 128; s > 0; s >>= 1) {
        if (tid < s) ssum[tid] += ssum[tid + s];
        __syncthreads();
    }
    if (tid == 0) g_bsum[blockIdx.x] = ssum[0];
}

__global__ __launch_bounds__(NBLK1) void reduce2_kernel(float* __restrict__ out) {
    __shared__ float ssum[NBLK1];
    int tid = threadIdx.x;
    ssum[tid] = g_bsum[tid];
    __syncthreads();
    #pragma unroll
    for (int s = NBLK1 / 2; s > 0; s >>= 1) {
        if (tid < s) ssum[tid] += ssum[tid + s];
        __syncthreads();
    }
    if (tid == 0) out[0] = ssum[0] * (1.0f / (float)(BB * NPTS));
}

// ---------------------------------------------------------------------------
extern "C" void kernel_launch(void* const* d_in, const int* in_sizes, int n_in,
                              void* d_out, int out_size) {
    const float* pred   = (const float*)d_in[0];   // [B, N, 3]
    const float* target = (const float*)d_in[1];   // [B, M, 3]
    float* out = (float*)d_out;

    static bool attr_set = false;
    if (!attr_set) {
        cudaFuncSetAttribute(chamfer_bb_kernel,
                             cudaFuncAttributeMaxDynamicSharedMemorySize,
                             NPTS * (int)sizeof(float4));
        attr_set = true;
    }

    bin_kernel<<<BB * 2, 512>>>(pred, target);
    cluster_kernel<<<(BB * NCLUS * 32) / 128, 128>>>();
    chamfer_bb_kernel<<<BB * 16, P3_TPB, NPTS * (int)sizeof(float4)>>>();
    reduce1_kernel<<<NBLK1, 256>>>();
    reduce2_kernel<<<1, NBLK1>>>(out);
}

// round 10
// speedup vs baseline: 2.1030x; 2.1030x over previous
#include <cuda_runtime.h>
#include <cstdint>

// Problem constants: B=32, N=M=4096, d=3
#define BB     32
#define NPTS   4096
#define NBINS  4096
#define NCHK   128                // 32-target chunks per batch
#define TPB    128
#define CPB    32                 // CTAs per batch
#define NBLK1  128

#define BIGF 3.4028235e38f

// ---- persistent scratch (no allocations allowed) --------------------------
__device__ float4 g_tgtS [BB * NPTS];   // x-sorted targets {x, y, z, 0.5|t|^2}
__device__ float4 g_predS[BB * NPTS];   // x-sorted preds  {-x,-y,-z,  |p|^2}
__device__ int    g_pidx [BB * NPTS];   // original pred index per sorted slot
__device__ float  g_dist [BB * NPTS];   // per-pred nearest distance (orig order)
__device__ float  g_bsum [NBLK1];

// ---------------------------------------------------------------------------
// P1: counting-sort by x (quantized to 4096 bins). One CTA per (batch,tensor).
// Exactness does NOT depend on quantization: the sweep uses exact per-chunk
// suffix-min / prefix-max of the stored x values.
// ---------------------------------------------------------------------------
__global__ __launch_bounds__(512) void bin_kernel(const float* __restrict__ pred,
                                                  const float* __restrict__ tgt) {
    __shared__ unsigned hist[NBINS];   // 16 KB
    __shared__ unsigned wsum[512];

    int b      = blockIdx.x >> 1;
    int isPred = blockIdx.x & 1;
    const float* src = (isPred ? pred : tgt) + (size_t)b * NPTS * 3;
    int tid = threadIdx.x;

    #pragma unroll
    for (int j = 0; j < NBINS / 512; j++) hist[tid + j * 512] = 0u;
    __syncthreads();

    unsigned mybin[8];
    #pragma unroll
    for (int j = 0; j < 8; j++) {
        int i = tid * 8 + j;
        float x = src[3 * i];
        int bx = __float2int_rd((x + 4.5f) * (4096.0f / 9.0f));
        mybin[j] = (unsigned)min(max(bx, 0), NBINS - 1);
        atomicAdd(&hist[mybin[j]], 1u);
    }
    __syncthreads();

    unsigned s = 0;
    #pragma unroll
    for (int j = 0; j < 8; j++) s += hist[tid * 8 + j];
    wsum[tid] = s;
    __syncthreads();
    #pragma unroll
    for (int off = 1; off < 512; off <<= 1) {
        unsigned v = wsum[tid];
        unsigned a = (tid >= off) ? wsum[tid - off] : 0u;
        __syncthreads();
        wsum[tid] = v + a;
        __syncthreads();
    }
    unsigned run = wsum[tid] - s;
    #pragma unroll
    for (int j = 0; j < 8; j++) {
        unsigned c = hist[tid * 8 + j];
        hist[tid * 8 + j] = run;
        run += c;
    }
    __syncthreads();

    float4* dst = (isPred ? g_predS : g_tgtS) + b * NPTS;
    int*    pix = g_pidx + b * NPTS;
    #pragma unroll
    for (int j = 0; j < 8; j++) {
        int i = tid * 8 + j;
        unsigned pos = atomicAdd(&hist[mybin[j]], 1u);
        float x = src[3 * i], y = src[3 * i + 1], z = src[3 * i + 2];
        float n2 = x * x + y * y + z * z;
        if (isPred) {
            dst[pos] = make_float4(-x, -y, -z, n2);
            pix[pos] = i;
        } else {
            dst[pos] = make_float4(x, y, z, 0.5f * n2);
        }
    }
}

// ---------------------------------------------------------------------------
// P2: plane-sweep exact nearest-target.
//   r(p,t) = 0.5|t|^2 - p.t  (3 FFMA);  d^2 = |p|^2 + 2 r
//   Lower bound for chunk c (right): all slots >= 32c have tx >= sufMinX[c].
// Warp = 32 consecutive x-sorted preds; walks chunks outward with ballots.
// ---------------------------------------------------------------------------
__device__ __forceinline__ void eval_chunk(const float4* __restrict__ ct,
                                           float4 p, float& m0, float& m1) {
    #pragma unroll 8
    for (int i = 0; i < 32; i += 2) {
        float4 ta = ct[i];
        float4 tb = ct[i + 1];
        float ra = __fmaf_rn(p.z, ta.z, ta.w);
        float rb = __fmaf_rn(p.z, tb.z, tb.w);
        ra = __fmaf_rn(p.y, ta.y, ra);
        rb = __fmaf_rn(p.y, tb.y, rb);
        ra = __fmaf_rn(p.x, ta.x, ra);
        rb = __fmaf_rn(p.x, tb.x, rb);
        m0 = fminf(m0, ra);
        m1 = fminf(m1, rb);
    }
}

__global__ __launch_bounds__(TPB) void chamfer_sweep_kernel() {
    extern __shared__ float4 sT[];          // NPTS targets: 64 KB dynamic
    __shared__ float cmin[NCHK], cmax[NCHK];
    __shared__ float sufMin[NCHK], preMax[NCHK];

    int b    = blockIdx.x >> 5;             // CPB = 32
    int cb   = blockIdx.x & 31;
    int tid  = threadIdx.x;
    int lane = tid & 31;
    int wl   = tid >> 5;                    // warp-in-CTA: 0..3

    // stage the batch's target array
    const float4* gt = g_tgtS + b * NPTS;
    #pragma unroll
    for (int i = tid; i < NPTS; i += TPB) sT[i] = gt[i];
    __syncthreads();

    // per-chunk x min/max, then exact suffix-min / prefix-max over chunks
    if (tid < NCHK) {
        float mn = BIGF, mx = -BIGF;
        #pragma unroll 8
        for (int i = 0; i < 32; i++) {
            float x = sT[tid * 32 + i].x;
            mn = fminf(mn, x);
            mx = fmaxf(mx, x);
        }
        cmin[tid] = mn; cmax[tid] = mx;
    }
    __syncthreads();
    if (tid < NCHK) {
        float mn = BIGF;
        for (int j = tid; j < NCHK; j++) mn = fminf(mn, cmin[j]);
        sufMin[tid] = mn;
        float mx = -BIGF;
        for (int j = 0; j <= tid; j++) mx = fmaxf(mx, cmax[j]);
        preMax[tid] = mx;
    }
    __syncthreads();

    // warp -> pred block: interleave warps across CTAs for load balance
    int wb = wl * CPB + cb;                 // 0..127
    int ip = wb * 32 + lane;
    float4 p = g_predS[b * NPTS + ip];      // {-x,-y,-z, |p|^2}
    int pidx = g_pidx [b * NPTS + ip];

    // probe the rank-matched chunk
    float m0 = BIGF, m1 = BIGF;
    eval_chunk(sT + wb * 32, p, m0, m1);
    float d2 = __fmaf_rn(2.0f, fminf(m0, m1), p.w);

    // right walk
    for (int c = wb + 1; c < NCHK; c++) {
        float bnd = sufMin[c] + p.x;        // = sufMinX - px
        bool active = !(bnd > 0.0f && bnd * bnd >= d2);
        if (!__ballot_sync(0xffffffffu, active)) break;
        eval_chunk(sT + c * 32, p, m0, m1);
        d2 = __fmaf_rn(2.0f, fminf(m0, m1), p.w);
    }
    // left walk
    for (int c = wb - 1; c >= 0; c--) {
        float bnd = -(preMax[c] + p.x);     // = px - preMaxX
        bool active = !(bnd > 0.0f && bnd * bnd >= d2);
        if (!__ballot_sync(0xffffffffu, active)) break;
        eval_chunk(sT + c * 32, p, m0, m1);
        d2 = __fmaf_rn(2.0f, fminf(m0, m1), p.w);
    }

    g_dist[b * NPTS + pidx] = sqrtf(fmaxf(d2, 0.0f));
}

// ---------------------------------------------------------------------------
// Reductions: fixed-order, deterministic
// ---------------------------------------------------------------------------
__global__ __launch_bounds__(256) void reduce1_kernel() {
    __shared__ float ssum[256];
    int tid = threadIdx.x;
    const int per_block = (BB * NPTS) / NBLK1;   // 1024
    float acc = 0.0f;
    #pragma unroll
    for (int k = 0; k < per_block / 256; k++)
        acc += g_dist[blockIdx.x * per_block + k * 256 + tid];
    ssum[tid] = acc;
    __syncthreads();
    #pragma unroll
    for (int s = 128; s > 0; s >>= 1) {
        if (tid < s) ssum[tid] += ssum[tid + s];
        __syncthreads();
    }
    if (tid == 0) g_bsum[blockIdx.x] = ssum[0];
}

__global__ __launch_bounds__(NBLK1) void reduce2_kernel(float* __restrict__ out) {
    __shared__ float ssum[NBLK1];
    int tid = threadIdx.x;
    ssum[tid] = g_bsum[tid];
    __syncthreads();
    #pragma unroll
    for (int s = NBLK1 / 2; s > 0; s >>= 1) {
        if (tid < s) ssum[tid] += ssum[tid + s];
        __syncthreads();
    }
    if (tid == 0) out[0] = ssum[0] * (1.0f / (float)(BB * NPTS));
}

// ---------------------------------------------------------------------------
extern "C" void kernel_launch(void* const* d_in, const int* in_sizes, int n_in,
                              void* d_out, int out_size) {
    const float* pred   = (const float*)d_in[0];   // [B, N, 3]
    const float* target = (const float*)d_in[1];   // [B, M, 3]
    float* out = (float*)d_out;

    static bool attr_set = false;
    if (!attr_set) {
        cudaFuncSetAttribute(chamfer_sweep_kernel,
                             cudaFuncAttributeMaxDynamicSharedMemorySize,
                             NPTS * (int)sizeof(float4));
        attr_set = true;
    }

    bin_kernel<<<BB * 2, 512>>>(pred, target);
    chamfer_sweep_kernel<<<BB * CPB, TPB, NPTS * (int)sizeof(float4)>>>();
    reduce1_kernel<<<NBLK1, 256>>>();
    reduce2_kernel<<<1, NBLK1>>>(out);
}

// round 13
// speedup vs baseline: 2.5534x; 1.2142x over previous
#include <cuda_runtime.h>
#include <cstdint>

// Problem constants: B=32, N=M=4096, d=3
#define BB     32
#define NPTS   4096
#define NBINS  4096               // 16 x-levels * 256 y-bins
#define NCHK   128                // 32-target chunks per batch
#define TPB    512
#define CPB    8                  // CTAs per batch  (BB*CPB = 256 CTAs total)
#define NBLK1  128

#define BIGF 3.4028235e38f

// ---- persistent scratch (no allocations allowed) --------------------------
__device__ float4 g_tgtS [BB * NPTS];   // sorted targets {x, y, z, 0.5|t|^2}
__device__ float4 g_predS[BB * NPTS];   // sorted preds  {-x,-y,-z,  |p|^2}
__device__ int    g_pidx [BB * NPTS];   // original pred index per sorted slot
__device__ float  g_dist [BB * NPTS];   // per-pred nearest distance (orig order)
__device__ float  g_bsum [NBLK1];

// ---------------------------------------------------------------------------
// Sort key: 16 x-levels (N(0,1) quantiles; exactness does NOT depend on this —
// all bounds are computed from actual data) * 256 y-bins.
// ---------------------------------------------------------------------------
__device__ __forceinline__ unsigned sort_key(float x, float y) {
    const float t0 = -1.5341f, t1 = -1.1503f, t2 = -0.8871f, t3 = -0.6745f,
                t4 = -0.4888f, t5 = -0.3186f, t6 = -0.1573f, t7 = 0.0f,
                t8 =  0.1573f, t9 =  0.3186f, tA =  0.4888f, tB =  0.6745f,
                tC =  0.8871f, tD =  1.1503f, tE =  1.5341f;
    int lvl = (x > t0) + (x > t1) + (x > t2) + (x > t3) + (x > t4) +
              (x > t5) + (x > t6) + (x > t7) + (x > t8) + (x > t9) +
              (x > tA) + (x > tB) + (x > tC) + (x > tD) + (x > tE);
    int yb = min(max(__float2int_rd((y + 4.5f) * (256.0f / 9.0f)), 0), 255);
    return (unsigned)(lvl * 256 + yb);
}

// ---------------------------------------------------------------------------
// P1: counting-sort by (x-level, y-bin). One CTA per (batch, tensor).
// ---------------------------------------------------------------------------
__global__ __launch_bounds__(512) void bin_kernel(const float* __restrict__ pred,
                                                  const float* __restrict__ tgt) {
    __shared__ unsigned hist[NBINS];   // 16 KB
    __shared__ unsigned wsum[512];

    int b      = blockIdx.x >> 1;
    int isPred = blockIdx.x & 1;
    const float* src = (isPred ? pred : tgt) + (size_t)b * NPTS * 3;
    int tid = threadIdx.x;

    #pragma unroll
    for (int j = 0; j < NBINS / 512; j++) hist[tid + j * 512] = 0u;
    __syncthreads();

    unsigned mybin[8];
    #pragma unroll
    for (int j = 0; j < 8; j++) {
        int i = tid * 8 + j;
        mybin[j] = sort_key(src[3 * i], src[3 * i + 1]);
        atomicAdd(&hist[mybin[j]], 1u);
    }
    __syncthreads();

    unsigned s = 0;
    #pragma unroll
    for (int j = 0; j < 8; j++) s += hist[tid * 8 + j];
    wsum[tid] = s;
    __syncthreads();
    #pragma unroll
    for (int off = 1; off < 512; off <<= 1) {
        unsigned v = wsum[tid];
        unsigned a = (tid >= off) ? wsum[tid - off] : 0u;
        __syncthreads();
        wsum[tid] = v + a;
        __syncthreads();
    }
    unsigned run = wsum[tid] - s;
    #pragma unroll
    for (int j = 0; j < 8; j++) {
        unsigned c = hist[tid * 8 + j];
        hist[tid * 8 + j] = run;
        run += c;
    }
    __syncthreads();

    float4* dst = (isPred ? g_predS : g_tgtS) + b * NPTS;
    int*    pix = g_pidx + b * NPTS;
    #pragma unroll
    for (int j = 0; j < 8; j++) {
        int i = tid * 8 + j;
        unsigned pos = atomicAdd(&hist[mybin[j]], 1u);
        float x = src[3 * i], y = src[3 * i + 1], z = src[3 * i + 2];
        float n2 = x * x + y * y + z * z;
        if (isPred) {
            dst[pos] = make_float4(-x, -y, -z, n2);
            pix[pos] = i;
        } else {
            dst[pos] = make_float4(x, y, z, 0.5f * n2);
        }
    }
}

// ---------------------------------------------------------------------------
// P2: exact NN with per-chunk AABB pruning (warp-collective survivor test).
//   r(p,t) = 0.5|t|^2 - p.t  (3 FFMA);  d^2 = |p|^2 + 2 r
// ---------------------------------------------------------------------------
__device__ __forceinline__ void eval_chunk(const float4* __restrict__ ct,
                                           float4 p, float& m0, float& m1) {
    #pragma unroll 8
    for (int i = 0; i < 32; i += 2) {
        float4 ta = ct[i];
        float4 tb = ct[i + 1];
        float ra = __fmaf_rn(p.z, ta.z, ta.w);
        float rb = __fmaf_rn(p.z, tb.z, tb.w);
        ra = __fmaf_rn(p.y, ta.y, ra);
        rb = __fmaf_rn(p.y, tb.y, rb);
        ra = __fmaf_rn(p.x, ta.x, ra);
        rb = __fmaf_rn(p.x, tb.x, rb);
        m0 = fminf(m0, ra);
        m1 = fminf(m1, rb);
    }
}

// point-to-box squared distance in xy
__device__ __forceinline__ float aabb_lb2(float4 bb, float px, float py) {
    float dx = fmaxf(0.0f, fmaxf(bb.x - px, px - bb.y));
    float dy = fmaxf(0.0f, fmaxf(bb.z - py, py - bb.w));
    return __fmaf_rn(dx, dx, dy * dy);
}

// box-to-box squared distance in xy: chunk bb vs warp box [wmnx,wmxx]x[wmny,wmxy]
__device__ __forceinline__ float box_lb2(float4 bb, float wmnx, float wmxx,
                                         float wmny, float wmxy) {
    float dx = fmaxf(0.0f, fmaxf(bb.x - wmxx, wmnx - bb.y));
    float dy = fmaxf(0.0f, fmaxf(bb.z - wmxy, wmny - bb.w));
    return __fmaf_rn(dx, dx, dy * dy);
}

__global__ __launch_bounds__(TPB) void chamfer_grid_kernel() {
    extern __shared__ float4 sT[];          // NPTS targets: 64 KB dynamic
    __shared__ float4 sBB[NCHK];            // per-chunk {minx, maxx, miny, maxy}

    int b    = blockIdx.x >> 3;             // CPB = 8
    int cb   = blockIdx.x & 7;
    int tid  = threadIdx.x;
    int lane = tid & 31;
    int wl   = tid >> 5;                    // 0..15

    const float4* gt = g_tgtS + b * NPTS;
    #pragma unroll
    for (int i = tid; i < NPTS; i += TPB) sT[i] = gt[i];
    __syncthreads();

    if (tid < NCHK) {
        float mnx = BIGF, mxx = -BIGF, mny = BIGF, mxy = -BIGF;
        #pragma unroll 8
        for (int i = 0; i < 32; i++) {
            float4 t = sT[tid * 32 + i];
            mnx = fminf(mnx, t.x); mxx = fmaxf(mxx, t.x);
            mny = fminf(mny, t.y); mxy = fmaxf(mxy, t.y);
        }
        sBB[tid] = make_float4(mnx, mxx, mny, mxy);
    }
    __syncthreads();

    int wb = wl * CPB + cb;                 // 0..127 (interleaved for balance)
    int ip = wb * 32 + lane;
    float4 p = g_predS[b * NPTS + ip];      // {-x,-y,-z, |p|^2}
    int pidx = g_pidx [b * NPTS + ip];
    float px = -p.x, py = -p.y;

    // probe: rank-matched xy column -> initial upper bound
    float m0 = BIGF, m1 = BIGF;
    eval_chunk(sT + wb * 32, p, m0, m1);
    float d2 = fmaxf(__fmaf_rn(2.0f, fminf(m0, m1), p.w), 0.0f);

    // warp-collective bound: pred xy-AABB and max d2 over lanes
    float wmnx = px, wmxx = px, wmny = py, wmxy = py, d2max = d2;
    #pragma unroll
    for (int o = 16; o; o >>= 1) {
        wmnx  = fminf(wmnx,  __shfl_xor_sync(0xffffffffu, wmnx,  o));
        wmxx  = fmaxf(wmxx,  __shfl_xor_sync(0xffffffffu, wmxx,  o));
        wmny  = fminf(wmny,  __shfl_xor_sync(0xffffffffu, wmny,  o));
        wmxy  = fmaxf(wmxy,  __shfl_xor_sync(0xffffffffu, wmxy,  o));
        d2max = fmaxf(d2max, __shfl_xor_sync(0xffffffffu, d2max, o));
    }

    // survivor masks: lane tests chunks lane, lane+32, lane+64, lane+96
    // against the WARP box + WARP max bound (true conservative union:
    // box-box dist <= any lane's point-box dist, d2max >= any lane's d2)
    unsigned masks[4];
    #pragma unroll
    for (int g = 0; g < 4; g++) {
        int k = g * 32 + lane;
        float lb = box_lb2(sBB[k], wmnx, wmxx, wmny, wmxy);
        bool keep = lb <= __fmaf_rn(d2max, 1.0001f, 1e-7f);
        masks[g] = __ballot_sync(0xffffffffu, keep);
    }
    masks[wb >> 5] &= ~(1u << (wb & 31));   // probe already evaluated

    // walk survivors (warp-uniform); per-lane point-box re-check against the
    // shrinking d2, unioned by ballot, before paying the 96-FFMA eval
    #pragma unroll
    for (int g = 0; g < 4; g++) {
        unsigned ms = masks[g];
        while (ms) {
            int k = g * 32 + (__ffs(ms) - 1);
            ms &= ms - 1;
            float lb = aabb_lb2(sBB[k], px, py);
            bool need = lb <= __fmaf_rn(d2, 1.0001f, 1e-7f);
            if (__ballot_sync(0xffffffffu, need)) {
                eval_chunk(sT + k * 32, p, m0, m1);
                d2 = fmaxf(__fmaf_rn(2.0f, fminf(m0, m1), p.w), 0.0f);
            }
        }
    }

    g_dist[b * NPTS + pidx] = sqrtf(d2);
}

// ---------------------------------------------------------------------------
// Reductions: fixed original-index order -> bitwise deterministic
// ---------------------------------------------------------------------------
__global__ __launch_bounds__(256) void reduce1_kernel() {
    __shared__ float ssum[256];
    int tid = threadIdx.x;
    const int per_block = (BB * NPTS) / NBLK1;   // 1024
    float acc = 0.0f;
    #pragma unroll
    for (int k = 0; k < per_block / 256; k++)
        acc += g_dist[blockIdx.x * per_block + k * 256 + tid];
    ssum[tid] = acc;
    __syncthreads();
    #pragma unroll
    for (int s = 128; s > 0; s >>= 1) {
        if (tid < s) ssum[tid] += ssum[tid + s];
        __syncthreads();
    }
    if (tid == 0) g_bsum[blockIdx.x] = ssum[0];
}

__global__ __launch_bounds__(NBLK1) void reduce2_kernel(float* __restrict__ out) {
    __shared__ float ssum[NBLK1];
    int tid = threadIdx.x;
    ssum[tid] = g_bsum[tid];
    __syncthreads();
    #pragma unroll
    for (int s = NBLK1 / 2; s > 0; s >>= 1) {
        if (tid < s) ssum[tid] += ssum[tid + s];
        __syncthreads();
    }
    if (tid == 0) out[0] = ssum[0] * (1.0f / (float)(BB * NPTS));
}

// ---------------------------------------------------------------------------
extern "C" void kernel_launch(void* const* d_in, const int* in_sizes, int n_in,
                              void* d_out, int out_size) {
    const float* pred   = (const float*)d_in[0];   // [B, N, 3]
    const float* target = (const float*)d_in[1];   // [B, M, 3]
    float* out = (float*)d_out;

    static bool attr_set = false;
    if (!attr_set) {
        cudaFuncSetAttribute(chamfer_grid_kernel,
                             cudaFuncAttributeMaxDynamicSharedMemorySize,
                             NPTS * (int)sizeof(float4));
        attr_set = true;
    }

    bin_kernel<<<BB * 2, 512>>>(pred, target);
    chamfer_grid_kernel<<<BB * CPB, TPB, NPTS * (int)sizeof(float4)>>>();
    reduce1_kernel<<<NBLK1, 256>>>();
    reduce2_kernel<<<1, NBLK1>>>(out);
}

// round 14
// speedup vs baseline: 2.6292x; 1.0297x over previous
#include <cuda_runtime.h>
#include <cstdint>

// Problem constants: B=32, N=M=4096, d=3
#define BB     32
#define NPTS   4096
#define NBINS  256                // 16 x-quantiles * 16 y-quantiles
#define NCHK   256                // 16-target chunks per batch
#define CSZ    16
#define NGRP   8                  // chunk groups of 32
#define TPB    512
#define CPB    8                  // CTAs per batch  (256 CTAs total)
#define NBLK1  128

#define BIGF 3.4028235e38f

// ---- persistent scratch (no allocations allowed) --------------------------
__device__ float4 g_tgtS [BB * NPTS];   // sorted targets {x, y, z, 0.5|t|^2}
__device__ float4 g_predS[BB * NPTS];   // sorted preds  {-x,-y,-z,  |p|^2}
__device__ int    g_pidx [BB * NPTS];   // original pred index per sorted slot
__device__ float  g_dist [BB * NPTS];   // per-pred nearest distance (orig order)
__device__ float  g_bsum [NBLK1];

// ---------------------------------------------------------------------------
// Equal-count key: 16 N(0,1) quantile levels in x AND y (tails can't create
// near-empty bins). Exactness never depends on this — all bounds are data-
// derived AABBs.
// ---------------------------------------------------------------------------
__device__ __forceinline__ int qlvl16(float v) {
    const float t0 = -1.5341f, t1 = -1.1503f, t2 = -0.8871f, t3 = -0.6745f,
                t4 = -0.4888f, t5 = -0.3186f, t6 = -0.1573f, t7 = 0.0f,
                t8 =  0.1573f, t9 =  0.3186f, tA =  0.4888f, tB =  0.6745f,
                tC =  0.8871f, tD =  1.1503f, tE =  1.5341f;
    return (v > t0) + (v > t1) + (v > t2) + (v > t3) + (v > t4) +
           (v > t5) + (v > t6) + (v > t7) + (v > t8) + (v > t9) +
           (v > tA) + (v > tB) + (v > tC) + (v > tD) + (v > tE);
}
__device__ __forceinline__ unsigned sort_key(float x, float y) {
    return (unsigned)(qlvl16(x) * 16 + qlvl16(y));
}

// ---------------------------------------------------------------------------
// P1: counting-sort by (x-quantile, y-quantile). One CTA per (batch, tensor).
// ---------------------------------------------------------------------------
__global__ __launch_bounds__(512) void bin_kernel(const float* __restrict__ pred,
                                                  const float* __restrict__ tgt) {
    __shared__ unsigned hist[NBINS];
    __shared__ unsigned wsum[512];

    int b      = blockIdx.x >> 1;
    int isPred = blockIdx.x & 1;
    const float* src = (isPred ? pred : tgt) + (size_t)b * NPTS * 3;
    int tid = threadIdx.x;

    if (tid < NBINS) hist[tid] = 0u;
    __syncthreads();

    unsigned mybin[8];
    #pragma unroll
    for (int j = 0; j < 8; j++) {
        int i = tid * 8 + j;
        mybin[j] = sort_key(src[3 * i], src[3 * i + 1]);
        atomicAdd(&hist[mybin[j]], 1u);
    }
    __syncthreads();

    unsigned s = (tid < NBINS) ? hist[tid] : 0u;
    wsum[tid] = s;
    __syncthreads();
    #pragma unroll
    for (int off = 1; off < 512; off <<= 1) {
        unsigned v = wsum[tid];
        unsigned a = (tid >= off) ? wsum[tid - off] : 0u;
        __syncthreads();
        wsum[tid] = v + a;
        __syncthreads();
    }
    if (tid < NBINS) hist[tid] = wsum[tid] - s;   // exclusive base
    __syncthreads();

    float4* dst = (isPred ? g_predS : g_tgtS) + b * NPTS;
    int*    pix = g_pidx + b * NPTS;
    #pragma unroll
    for (int j = 0; j < 8; j++) {
        int i = tid * 8 + j;
        unsigned pos = atomicAdd(&hist[mybin[j]], 1u);
        float x = src[3 * i], y = src[3 * i + 1], z = src[3 * i + 2];
        float n2 = x * x + y * y + z * z;
        if (isPred) {
            dst[pos] = make_float4(-x, -y, -z, n2);
            pix[pos] = i;
        } else {
            dst[pos] = make_float4(x, y, z, 0.5f * n2);
        }
    }
}

// ---------------------------------------------------------------------------
// P2: exact NN, AABB-pruned, contracting near-to-far group walk.
//   r(p,t) = 0.5|t|^2 - p.t  (3 FFMA);  d^2 = |p|^2 + 2 r
// ---------------------------------------------------------------------------
__device__ __forceinline__ void eval_chunk(const float4* __restrict__ ct,
                                           float4 p, float& m0, float& m1) {
    #pragma unroll
    for (int i = 0; i < CSZ; i += 2) {
        float4 ta = ct[i];
        float4 tb = ct[i + 1];
        float ra = __fmaf_rn(p.z, ta.z, ta.w);
        float rb = __fmaf_rn(p.z, tb.z, tb.w);
        ra = __fmaf_rn(p.y, ta.y, ra);
        rb = __fmaf_rn(p.y, tb.y, rb);
        ra = __fmaf_rn(p.x, ta.x, ra);
        rb = __fmaf_rn(p.x, tb.x, rb);
        m0 = fminf(m0, ra);
        m1 = fminf(m1, rb);
    }
}

__device__ __forceinline__ float aabb_lb2(float4 bb, float px, float py) {
    float dx = fmaxf(0.0f, fmaxf(bb.x - px, px - bb.y));
    float dy = fmaxf(0.0f, fmaxf(bb.z - py, py - bb.w));
    return __fmaf_rn(dx, dx, dy * dy);
}

__device__ __forceinline__ float box_lb2(float4 bb, float wmnx, float wmxx,
                                         float wmny, float wmxy) {
    float dx = fmaxf(0.0f, fmaxf(bb.x - wmxx, wmnx - bb.y));
    float dy = fmaxf(0.0f, fmaxf(bb.z - wmxy, wmny - bb.w));
    return __fmaf_rn(dx, dx, dy * dy);
}

__device__ __forceinline__ float warp_max(float v) {
    #pragma unroll
    for (int o = 16; o; o >>= 1)
        v = fmaxf(v, __shfl_xor_sync(0xffffffffu, v, o));
    return v;
}

__global__ __launch_bounds__(TPB) void chamfer_grid_kernel() {
    extern __shared__ float4 sT[];          // NPTS targets: 64 KB dynamic
    __shared__ float4 sBB[NCHK];            // per-chunk {minx, maxx, miny, maxy}

    int b    = blockIdx.x >> 3;             // CPB = 8
    int cb   = blockIdx.x & 7;
    int tid  = threadIdx.x;
    int lane = tid & 31;
    int wl   = tid >> 5;                    // 0..15

    const float4* gt = g_tgtS + b * NPTS;
    #pragma unroll
    for (int i = tid; i < NPTS; i += TPB) sT[i] = gt[i];
    __syncthreads();

    if (tid < NCHK) {
        float mnx = BIGF, mxx = -BIGF, mny = BIGF, mxy = -BIGF;
        #pragma unroll
        for (int i = 0; i < CSZ; i++) {
            float4 t = sT[tid * CSZ + i];
            mnx = fminf(mnx, t.x); mxx = fmaxf(mxx, t.x);
            mny = fminf(mny, t.y); mxy = fmaxf(mxy, t.y);
        }
        sBB[tid] = make_float4(mnx, mxx, mny, mxy);
    }
    __syncthreads();

    int wb = wl * CPB + cb;                 // warp block 0..127 (interleaved)
    int ip = wb * 32 + lane;
    float4 p = g_predS[b * NPTS + ip];      // {-x,-y,-z, |p|^2}
    int pidx = g_pidx [b * NPTS + ip];
    float px = -p.x, py = -p.y;

    // probe BOTH chunks of the warp's rank range (32 targets)
    int cpair = 2 * wb;                     // chunks cpair, cpair+1
    float m0 = BIGF, m1 = BIGF;
    eval_chunk(sT + cpair * CSZ, p, m0, m1);
    eval_chunk(sT + (cpair + 1) * CSZ, p, m0, m1);
    float d2 = fmaxf(__fmaf_rn(2.0f, fminf(m0, m1), p.w), 0.0f);

    // warp pred-box (fixed) — d2max is recomputed lazily per group
    float wmnx = px, wmxx = px, wmny = py, wmxy = py;
    #pragma unroll
    for (int o = 16; o; o >>= 1) {
        wmnx = fminf(wmnx, __shfl_xor_sync(0xffffffffu, wmnx, o));
        wmxx = fmaxf(wmxx, __shfl_xor_sync(0xffffffffu, wmxx, o));
        wmny = fminf(wmny, __shfl_xor_sync(0xffffffffu, wmny, o));
        wmxy = fmaxf(wmxy, __shfl_xor_sync(0xffffffffu, wmxy, o));
    }

    // near-to-far group order around the warp's own group
    int go = cpair >> 5;                    // warp-uniform
    int order[NGRP];
    {
        int idx = 0;
        order[idx++] = go;
        for (int d = 1; d < NGRP && idx < NGRP; d++) {
            if (go + d < NGRP) order[idx++] = go + d;
            if (go - d >= 0 && idx < NGRP) order[idx++] = go - d;
        }
    }

    #pragma unroll 1
    for (int oi = 0; oi < NGRP; oi++) {
        int g = order[oi];
        // contracting warp-collective bound
        float d2m = warp_max(d2);
        int k = g * 32 + lane;
        float lbw = box_lb2(sBB[k], wmnx, wmxx, wmny, wmxy);
        bool keep = lbw <= __fmaf_rn(d2m, 1.0001f, 1e-7f);
        unsigned ms = __ballot_sync(0xffffffffu, keep);
        if (g == go) ms &= ~(3u << (cpair & 31));   // probes already done

        while (ms) {
            int k2 = g * 32 + (__ffs(ms) - 1);
            ms &= ms - 1;
            float lb = aabb_lb2(sBB[k2], px, py);
            bool need = lb <= __fmaf_rn(d2, 1.0001f, 1e-7f);
            if (__ballot_sync(0xffffffffu, need)) {
                eval_chunk(sT + k2 * CSZ, p, m0, m1);
                d2 = fmaxf(__fmaf_rn(2.0f, fminf(m0, m1), p.w), 0.0f);
            }
        }
    }

    g_dist[b * NPTS + pidx] = sqrtf(d2);
}

// ---------------------------------------------------------------------------
// Reductions: fixed original-index order -> bitwise deterministic
// ---------------------------------------------------------------------------
__global__ __launch_bounds__(256) void reduce1_kernel() {
    __shared__ float ssum[256];
    int tid = threadIdx.x;
    const int per_block = (BB * NPTS) / NBLK1;   // 1024
    float acc = 0.0f;
    #pragma unroll
    for (int k = 0; k < per_block / 256; k++)
        acc += g_dist[blockIdx.x * per_block + k * 256 + tid];
    ssum[tid] = acc;
    __syncthreads();
    #pragma unroll
    for (int s = 128; s > 0; s >>= 1) {
        if (tid < s) ssum[tid] += ssum[tid + s];
        __syncthreads();
    }
    if (tid == 0) g_bsum[blockIdx.x] = ssum[0];
}

__global__ __launch_bounds__(NBLK1) void reduce2_kernel(float* __restrict__ out) {
    __shared__ float ssum[NBLK1];
    int tid = threadIdx.x;
    ssum[tid] = g_bsum[tid];
    __syncthreads();
    #pragma unroll
    for (int s = NBLK1 / 2; s > 0; s >>= 1) {
        if (tid < s) ssum[tid] += ssum[tid + s];
        __syncthreads();
    }
    if (tid == 0) out[0] = ssum[0] * (1.0f / (float)(BB * NPTS));
}

// ---------------------------------------------------------------------------
extern "C" void kernel_launch(void* const* d_in, const int* in_sizes, int n_in,
                              void* d_out, int out_size) {
    const float* pred   = (const float*)d_in[0];   // [B, N, 3]
    const float* target = (const float*)d_in[1];   // [B, M, 3]
    float* out = (float*)d_out;

    static bool attr_set = false;
    if (!attr_set) {
        cudaFuncSetAttribute(chamfer_grid_kernel,
                             cudaFuncAttributeMaxDynamicSharedMemorySize,
                             NPTS * (int)sizeof(float4));
        attr_set = true;
    }

    bin_kernel<<<BB * 2, 512>>>(pred, target);
    chamfer_grid_kernel<<<BB * CPB, TPB, NPTS * (int)sizeof(float4)>>>();
    reduce1_kernel<<<NBLK1, 256>>>();
    reduce2_kernel<<<1, NBLK1>>>(out);
}